// round 10
// baseline (speedup 1.0000x reference)
#include <cuda_runtime.h>
#include <cuda_fp16.h>

#define BATCH 8
#define CCH   128
#define NTOK  16384
#define HEADS 8
#define LN_EPS 1e-5f

// ---------------- device scratch ----------------
__device__ float  g_kv[BATCH * HEADS * 16 * 16];
__device__ __half g_wkv[256 * 128];
__device__ __half g_o1h[128 * 128];
__device__ __half g_o2h[128 * 128];
__device__ __half g_meff[BATCH * 128 * 128];
__device__ float  g_meffb[BATCH * 128];
__device__ __half g_x16[(size_t)BATCH * CCH * NTOK];

// ---------------- helpers ----------------
__device__ __forceinline__ unsigned pk2h(float a, float b) {
    __half2 h = __floats2half2_rn(a, b);
    return *reinterpret_cast<unsigned*>(&h);
}

__device__ __forceinline__ void mma16816h(float* c, const unsigned* a, const unsigned* b) {
    asm volatile(
        "mma.sync.aligned.m16n8k16.row.col.f32.f16.f16.f32 "
        "{%0,%1,%2,%3}, {%4,%5,%6,%7}, {%8,%9}, {%0,%1,%2,%3};\n"
        : "+f"(c[0]), "+f"(c[1]), "+f"(c[2]), "+f"(c[3])
        : "r"(a[0]), "r"(a[1]), "r"(a[2]), "r"(a[3]), "r"(b[0]), "r"(b[1]));
}

__device__ __forceinline__ unsigned smem_u32(const void* p) {
    return (unsigned)__cvta_generic_to_shared(p);
}

__device__ __forceinline__ void ldsm4(unsigned& r0, unsigned& r1, unsigned& r2, unsigned& r3,
                                      unsigned addr) {
    asm volatile("ldmatrix.sync.aligned.m8n8.x4.shared.b16 {%0,%1,%2,%3}, [%4];\n"
                 : "=r"(r0), "=r"(r1), "=r"(r2), "=r"(r3) : "r"(addr));
}

__device__ __forceinline__ void ldsm4t(unsigned& r0, unsigned& r1, unsigned& r2, unsigned& r3,
                                       unsigned addr) {
    asm volatile("ldmatrix.sync.aligned.m8n8.x4.trans.shared.b16 {%0,%1,%2,%3}, [%4];\n"
                 : "=r"(r0), "=r"(r1), "=r"(r2), "=r"(r3) : "r"(addr));
}

__device__ __forceinline__ void cpasync16(unsigned s, const void* g) {
    asm volatile("cp.async.cg.shared.global [%0], [%1], 16;\n" :: "r"(s), "l"(g));
}
#define CP_COMMIT() asm volatile("cp.async.commit_group;\n")
#define CP_WAIT(n)  asm volatile("cp.async.wait_group %0;\n" :: "n"(n))

__device__ __forceinline__ float rsqrt_fast(float x) {
    float r;
    asm("rsqrt.approx.f32 %0, %1;\n" : "=f"(r) : "f"(x));
    return r;
}

// packed-constant builder (constant-folded by ptxas)
__device__ __forceinline__ unsigned long long pkf2(float v) {
    unsigned u = __float_as_uint(v);
    return ((unsigned long long)u << 32) | (unsigned long long)u;
}

// GELU(exact-erf) on a pair of fp32 values using packed f32x2 math.
// Same numerics as A&S 7.1.26 with rcp.approx + ex2.approx (as before).
__device__ __forceinline__ void gelu2(float& va, float& vb) {
    unsigned long long H, Y, AY, Targ, T, P, S, Earg, E, R, HH, G;
    asm("mov.b64 %0, {%1, %2};" : "=l"(H) : "f"(va), "f"(vb));
    asm("mul.rn.f32x2 %0, %1, %2;" : "=l"(Y) : "l"(H), "l"(pkf2(0.70710678118654752f)));
    asm("and.b64 %0, %1, %2;" : "=l"(AY) : "l"(Y), "l"(0x7FFFFFFF7FFFFFFFULL));
    asm("fma.rn.f32x2 %0, %1, %2, %3;"
        : "=l"(Targ) : "l"(AY), "l"(pkf2(0.3275911f)), "l"(pkf2(1.0f)));
    {
        float t0, t1;
        asm("mov.b64 {%0, %1}, %2;" : "=f"(t0), "=f"(t1) : "l"(Targ));
        asm("rcp.approx.f32 %0, %0;" : "+f"(t0));
        asm("rcp.approx.f32 %0, %0;" : "+f"(t1));
        asm("mov.b64 %0, {%1, %2};" : "=l"(T) : "f"(t0), "f"(t1));
    }
    asm("fma.rn.f32x2 %0, %1, %2, %3;"
        : "=l"(P) : "l"(pkf2(1.061405429f)), "l"(T), "l"(pkf2(-1.453152027f)));
    asm("fma.rn.f32x2 %0, %0, %1, %2;" : "+l"(P) : "l"(T), "l"(pkf2(1.421413741f)));
    asm("fma.rn.f32x2 %0, %0, %1, %2;" : "+l"(P) : "l"(T), "l"(pkf2(-0.284496736f)));
    asm("fma.rn.f32x2 %0, %0, %1, %2;" : "+l"(P) : "l"(T), "l"(pkf2(0.254829592f)));
    asm("mul.rn.f32x2 %0, %0, %1;" : "+l"(P) : "l"(T));
    asm("mul.rn.f32x2 %0, %1, %1;" : "=l"(S) : "l"(AY));
    asm("mul.rn.f32x2 %0, %1, %2;" : "=l"(Earg) : "l"(S), "l"(pkf2(-1.4426950408889634f)));
    {
        float e0, e1;
        asm("mov.b64 {%0, %1}, %2;" : "=f"(e0), "=f"(e1) : "l"(Earg));
        asm("ex2.approx.f32 %0, %0;" : "+f"(e0));
        asm("ex2.approx.f32 %0, %0;" : "+f"(e1));
        asm("mov.b64 %0, {%1, %2};" : "=l"(E) : "f"(e0), "f"(e1));
    }
    asm("xor.b64 %0, %0, %1;" : "+l"(P) : "l"(0x8000000080000000ULL));  // -p
    asm("fma.rn.f32x2 %0, %1, %2, %3;" : "=l"(R) : "l"(P), "l"(E), "l"(pkf2(1.0f)));  // erf(|y|)
    // copysign(R, Y)
    {
        unsigned long long Rm, Ys;
        asm("and.b64 %0, %1, %2;" : "=l"(Rm) : "l"(R), "l"(0x7FFFFFFF7FFFFFFFULL));
        asm("and.b64 %0, %1, %2;" : "=l"(Ys) : "l"(Y), "l"(0x8000000080000000ULL));
        asm("or.b64 %0, %1, %2;" : "=l"(R) : "l"(Rm), "l"(Ys));
    }
    asm("mul.rn.f32x2 %0, %1, %2;" : "=l"(HH) : "l"(H), "l"(pkf2(0.5f)));
    asm("fma.rn.f32x2 %0, %1, %2, %1;" : "=l"(G) : "l"(HH), "l"(R));  // 0.5h + 0.5h*erf
    asm("mov.b64 {%0, %1}, %2;" : "=f"(va), "=f"(vb) : "l"(G));
}

// Output-layout GEMM: C[c_out rows][token cols] = A[c_out][k=128] * B[k=128][t].
template <int NI8, int LDB>
__device__ __forceinline__ void gemm_t(const __half* __restrict__ A,
                                       const __half* __restrict__ B,
                                       float (&acc)[2][NI8][4], int rbase, int cbase, int lane) {
    unsigned a_addr = smem_u32(A + (rbase + (lane & 15)) * 136 + ((lane >> 4) << 3));
    unsigned b_addr = smem_u32(B + (lane & 15) * LDB + cbase + ((lane >> 4) << 3));
#pragma unroll
    for (int kc = 0; kc < 128; kc += 16) {
        unsigned a[2][4];
        ldsm4(a[0][0], a[0][1], a[0][2], a[0][3], a_addr);
        ldsm4(a[1][0], a[1][1], a[1][2], a[1][3], a_addr + 16 * 136 * 2);
#pragma unroll
        for (int g = 0; g < NI8 / 2; g++) {
            unsigned b0, b1, b2, b3;
            ldsm4t(b0, b1, b2, b3, b_addr + g * 32);
            unsigned bl[2] = {b0, b1}, bh[2] = {b2, b3};
            mma16816h(acc[0][2 * g],     a[0], bl);
            mma16816h(acc[1][2 * g],     a[1], bl);
            mma16816h(acc[0][2 * g + 1], a[0], bh);
            mma16816h(acc[1][2 * g + 1], a[1], bh);
        }
        a_addr += 32;
        b_addr += 16 * LDB * 2;
    }
}

// ---------------- kernel 0: weight prep ----------------
__global__ void prep_kernel(const float* __restrict__ qkv_w,
                            const float* __restrict__ o1_w,
                            const float* __restrict__ o2_w) {
    int idx = blockIdx.x * blockDim.x + threadIdx.x;
    int nthr = gridDim.x * blockDim.x;
    for (int i = idx; i < BATCH * HEADS * 16 * 16; i += nthr) g_kv[i] = 0.f;
    for (int i = idx; i < 256 * 128; i += nthr) {
        int r = i >> 7, c = i & 127;
        int h = r >> 5, j = r & 31;
        int src = (j < 16) ? (48 * h + 16 + j) : (48 * h + 32 + (j - 16));
        g_wkv[i] = __float2half_rn(qkv_w[src * 128 + c]);
    }
    for (int i = idx; i < 128 * 128; i += nthr) {
        g_o1h[i] = __float2half_rn(o1_w[i]);
        g_o2h[i] = __float2half_rn(o2_w[i]);
    }
}

// ---------------- kernel 1: x->fp16 + k,v projection + register-LN + register-kv MMA ----------------
// 512 threads, 4 tiles of 128 tokens per block (grid NTOK/512 x BATCH).
#define KV_TILES 4
#define KVS_WT   0
#define KVS_XT0  (256 * 136 * 2)
#define KVS_XT1  (KVS_XT0 + 128 * 136 * 2)
#define KVS_QB   (KVS_XT1 + 128 * 136 * 2)
#define KVS_SMEM (KVS_QB + 256 * 4)

__global__ void __launch_bounds__(512, 1) kv_kernel(const float* __restrict__ x,
                                                    const float* __restrict__ qkv_b,
                                                    const float* __restrict__ kln_w,
                                                    const float* __restrict__ kln_b,
                                                    const float* __restrict__ vln_w,
                                                    const float* __restrict__ vln_b) {
    extern __shared__ char smem[];
    __half* Wt = (__half*)(smem + KVS_WT);
    __half* xt0 = (__half*)(smem + KVS_XT0);
    __half* xt1 = (__half*)(smem + KVS_XT1);
    float* qb = (float*)(smem + KVS_QB);

    int tid = threadIdx.x;
    int b = blockIdx.y;
    const float* xb = x + (size_t)b * CCH * NTOK;
    __half* x16b = g_x16 + (size_t)b * CCH * NTOK;

    // weights via cp.async (group 0)
    {
        unsigned wt = smem_u32(Wt);
        for (int i = tid; i < 256 * 16; i += 512) {
            int r = i >> 4, c = i & 15;
            cpasync16(wt + r * 272 + c * 16, g_wkv + r * 128 + c * 8);
        }
        CP_COMMIT();
    }
    if (tid < 256) {
        int h = tid >> 5, j = tid & 31;
        int src_r = (j < 16) ? (48 * h + 16 + j) : (48 * h + 32 + (j - 16));
        qb[tid] = qkv_b[src_r];
    }

    int w = tid >> 5, l = tid & 31;
    int lr = l >> 2, lc = l & 3;
    int mw = w >> 1;      // head
    int nw = w & 1;       // token half
    int rbase = mw * 32, cbase = nw * 64;

    float lw[2][2], lb[2][2];
    lw[0][0] = kln_w[mw * 16 + lr];     lw[0][1] = kln_w[mw * 16 + lr + 8];
    lb[0][0] = kln_b[mw * 16 + lr];     lb[0][1] = kln_b[mw * 16 + lr + 8];
    lw[1][0] = vln_w[mw * 16 + lr];     lw[1][1] = vln_w[mw * 16 + lr + 8];
    lb[1][0] = vln_b[mw * 16 + lr];     lb[1][1] = vln_b[mw * 16 + lr + 8];

    float acc2[2][4];
#pragma unroll
    for (int e = 0; e < 2; e++)
#pragma unroll
        for (int q = 0; q < 4; q++) acc2[e][q] = 0.f;

#pragma unroll
    for (int tile = 0; tile < KV_TILES; tile++) {
        int n0 = blockIdx.x * (128 * KV_TILES) + tile * 128;
        __half* xt = (tile & 1) ? xt1 : xt0;

        // load fp32 x tile, convert, store to smem + g_x16
#pragma unroll
        for (int k = 0; k < 8; k++) {
            int i = tid + k * 512;
            int r = i >> 5, c4 = i & 31;
            float4 v = *(const float4*)(xb + (size_t)r * NTOK + n0 + c4 * 4);
            __half2 h0 = __floats2half2_rn(v.x, v.y);
            __half2 h1 = __floats2half2_rn(v.z, v.w);
            uint2 u;
            u.x = *reinterpret_cast<unsigned*>(&h0);
            u.y = *reinterpret_cast<unsigned*>(&h1);
            *(uint2*)(xt + r * 136 + c4 * 4) = u;
            *(uint2*)(x16b + (size_t)r * NTOK + n0 + c4 * 4) = u;
        }
        if (tile == 0) CP_WAIT(0);
        __syncthreads();

        float acc[2][8][4];
#pragma unroll
        for (int a_ = 0; a_ < 2; a_++)
#pragma unroll
            for (int b_ = 0; b_ < 8; b_++)
#pragma unroll
                for (int c_ = 0; c_ < 4; c_++) acc[a_][b_][c_] = 0.f;

        gemm_t<8, 136>(Wt, xt, acc, rbase, cbase, l);

        float q0 = qb[rbase + lr],      q1 = qb[rbase + lr + 8];
        float q2 = qb[rbase + 16 + lr], q3 = qb[rbase + 16 + lr + 8];
#pragma unroll
        for (int ni = 0; ni < 8; ni++) {
            acc[0][ni][0] += q0; acc[0][ni][1] += q0;
            acc[0][ni][2] += q1; acc[0][ni][3] += q1;
            acc[1][ni][0] += q2; acc[1][ni][1] += q2;
            acc[1][ni][2] += q3; acc[1][ni][3] += q3;
        }

        // register LayerNorm over d=16 (ddof=1, eps on std), half2-packed butterflies
        unsigned kf[8][2], vf[8][2];
#pragma unroll
        for (int mi = 0; mi < 2; mi++) {
#pragma unroll
            for (int ni = 0; ni < 8; ni++) {
                float* c = acc[mi][ni];
                __half2 s2 = __floats2half2_rn(c[0] + c[2], c[1] + c[3]);
                __half2 q2h = __floats2half2_rn(fmaf(c[0], c[0], c[2] * c[2]),
                                                fmaf(c[1], c[1], c[3] * c[3]));
                unsigned su = *reinterpret_cast<unsigned*>(&s2);
                unsigned qu = *reinterpret_cast<unsigned*>(&q2h);
#pragma unroll
                for (int m = 4; m <= 16; m <<= 1) {
                    unsigned so = __shfl_xor_sync(0xffffffffu, su, m);
                    unsigned qo = __shfl_xor_sync(0xffffffffu, qu, m);
                    __half2 rs2 = __hadd2(*reinterpret_cast<__half2*>(&su),
                                          *reinterpret_cast<__half2*>(&so));
                    __half2 rq2 = __hadd2(*reinterpret_cast<__half2*>(&qu),
                                          *reinterpret_cast<__half2*>(&qo));
                    su = *reinterpret_cast<unsigned*>(&rs2);
                    qu = *reinterpret_cast<unsigned*>(&rq2);
                }
                float2 s = __half22float2(*reinterpret_cast<__half2*>(&su));
                float2 q = __half22float2(*reinterpret_cast<__half2*>(&qu));
                float ma = s.x * (1.f / 16.f);
                float va = fmaxf((q.x - 16.f * ma * ma) * (1.f / 15.f), 1e-12f);
                float rsa = rsqrt_fast(va);
                float ia = fmaf(-LN_EPS * rsa, rsa, rsa);
                float mb = s.y * (1.f / 16.f);
                float vb = fmaxf((q.y - 16.f * mb * mb) * (1.f / 15.f), 1e-12f);
                float rsb = rsqrt_fast(vb);
                float ib = fmaf(-LN_EPS * rsb, rsb, rsb);
                float n0v = lw[mi][0] * ((c[0] - ma) * ia) + lb[mi][0];
                float n1v = lw[mi][0] * ((c[1] - mb) * ib) + lb[mi][0];
                float n2v = lw[mi][1] * ((c[2] - ma) * ia) + lb[mi][1];
                float n3v = lw[mi][1] * ((c[3] - mb) * ib) + lb[mi][1];
                unsigned lo = pk2h(n0v, n1v);
                unsigned hi = pk2h(n2v, n3v);
                if (mi == 0) { kf[ni][0] = lo; kf[ni][1] = hi; }
                else         { vf[ni][0] = lo; vf[ni][1] = hi; }
            }
        }

        // kv outer product entirely in registers
#pragma unroll
        for (int tc = 0; tc < 4; tc++) {
            unsigned a[4] = {kf[2 * tc][0], kf[2 * tc][1], kf[2 * tc + 1][0], kf[2 * tc + 1][1]};
            unsigned b0[2] = {vf[2 * tc][0], vf[2 * tc + 1][0]};
            unsigned b1[2] = {vf[2 * tc][1], vf[2 * tc + 1][1]};
            mma16816h(acc2[0], a, b0);
            mma16816h(acc2[1], a, b1);
        }
    }

    float* base = g_kv + (size_t)(b * HEADS + mw) * 256;
#pragma unroll
    for (int eh = 0; eh < 2; eh++) {
        int e0 = eh * 8 + lc * 2;
        atomicAdd(base + lr * 16 + e0,           acc2[eh][0]);
        atomicAdd(base + lr * 16 + e0 + 1,       acc2[eh][1]);
        atomicAdd(base + (lr + 8) * 16 + e0,     acc2[eh][2]);
        atomicAdd(base + (lr + 8) * 16 + e0 + 1, acc2[eh][3]);
    }
}

// ---------------- kernel 2: compose Meff_b = Wq o kv / N ----------------
__global__ void compose_kernel(const float* __restrict__ qkv_w, const float* __restrict__ qkv_b) {
    __shared__ float kvs[256];
    __shared__ float bsum[16];
    int g = blockIdx.x, b = blockIdx.y;
    int ci = threadIdx.x;

    for (int i = ci; i < 256; i += 128)
        kvs[i] = g_kv[(b * HEADS + g) * 256 + i] * (1.f / (float)NTOK);
    if (ci < 16) {
        float s = 0.f;
#pragma unroll
        for (int d = 0; d < 16; d++) s += qkv_b[48 * g + d] * kvs[d * 16 + ci];
        bsum[ci] = s;
    }
    __syncthreads();

    float wq[16];
#pragma unroll
    for (int d = 0; d < 16; d++) wq[d] = qkv_w[(48 * g + d) * 128 + ci];

    __half* mdst = g_meff + ((size_t)b * 128 + g * 16) * 128 + ci;
#pragma unroll
    for (int e = 0; e < 16; e++) {
        float s = 0.f;
#pragma unroll
        for (int d = 0; d < 16; d++) s += wq[d] * kvs[d * 16 + e];
        mdst[e * 128] = __float2half_rn(s);
    }
    if (ci < 16) g_meffb[b * 128 + g * 16 + ci] = bsum[ci];
}

// ---------------- kernel 3: fused av + residual + o1 + gelu + o2 + residual ----------------
#define M4_LDB  264
#define M4_XT   0
#define M4_RT   (128 * M4_LDB * 2)
#define M4_WA   (2 * 128 * M4_LDB * 2)
#define M4_WB   (M4_WA + 128 * 136 * 2)
#define M4_BIAS (M4_WB + 128 * 136 * 2)
#define M4_SMEM (M4_BIAS + 3 * 128 * 4)

__global__ void __launch_bounds__(512, 1) main_kernel(const float* __restrict__ o1_b,
                                                      const float* __restrict__ o2_b,
                                                      float* __restrict__ out) {
    extern __shared__ char smem[];
    __half* xt = (__half*)(smem + M4_XT);
    __half* rt = (__half*)(smem + M4_RT);
    __half* wA = (__half*)(smem + M4_WA);
    __half* wB = (__half*)(smem + M4_WB);
    float* bias = (float*)(smem + M4_BIAS);

    int tid = threadIdx.x;
    int b = blockIdx.y;
    int n0 = blockIdx.x * 256;

    {
        unsigned wa = smem_u32(wA), xa = smem_u32(xt);
        const __half* msrc = g_meff + (size_t)b * 128 * 128;
        const __half* xsrc = g_x16 + (size_t)b * CCH * NTOK + n0;
        for (int i = tid; i < 128 * 16; i += 512) {
            int r = i >> 4, c = i & 15;
            cpasync16(wa + r * 272 + c * 16, msrc + r * 128 + c * 8);
        }
        for (int i = tid; i < 128 * 32; i += 512) {
            int r = i >> 5, c = i & 31;
            cpasync16(xa + r * (M4_LDB * 2) + c * 16, xsrc + (size_t)r * NTOK + c * 8);
        }
        CP_COMMIT();
        unsigned wb = smem_u32(wB);
        for (int i = tid; i < 128 * 16; i += 512) {
            int r = i >> 4, c = i & 15;
            cpasync16(wb + r * 272 + c * 16, g_o1h + r * 128 + c * 8);
        }
        CP_COMMIT();
    }
    if (tid < 128) {
        bias[tid] = g_meffb[b * 128 + tid];
        bias[128 + tid] = o1_b[tid];
        bias[256 + tid] = o2_b[tid];
    }
    CP_WAIT(1);
    __syncthreads();

    int w = tid >> 5, l = tid & 31;
    int lr = l >> 2, lc = l & 3;
    int mw = w >> 2, nw = w & 3;
    int rbase = mw * 32, cbase = nw * 64;

    float acc[2][8][4];
#define ZACC() { _Pragma("unroll") for (int a_=0;a_<2;a_++) _Pragma("unroll") for (int b_=0;b_<8;b_++) _Pragma("unroll") for (int c_=0;c_<4;c_++) acc[a_][b_][c_]=0.f; }

    // ---- phase 1: rt = Meff*x + meffb + x ----
    ZACC();
    gemm_t<8, M4_LDB>(wA, xt, acc, rbase, cbase, l);
    {
        float bm0 = bias[rbase + lr],      bm1 = bias[rbase + lr + 8];
        float bm2 = bias[rbase + 16 + lr], bm3 = bias[rbase + 16 + lr + 8];
#pragma unroll
        for (int mi = 0; mi < 2; mi++) {
            int row = rbase + mi * 16 + lr;
            float ba0 = mi ? bm2 : bm0, ba1 = mi ? bm3 : bm1;
#pragma unroll
            for (int ni = 0; ni < 8; ni++) {
                int col = cbase + ni * 8 + lc * 2;
                __half2 xv0 = *(const __half2*)(xt + row * M4_LDB + col);
                __half2 xv1 = *(const __half2*)(xt + (row + 8) * M4_LDB + col);
                float2 f0 = __half22float2(xv0), f1 = __half22float2(xv1);
                float r00 = acc[mi][ni][0] + ba0 + f0.x;
                float r01 = acc[mi][ni][1] + ba0 + f0.y;
                float r10 = acc[mi][ni][2] + ba1 + f1.x;
                float r11 = acc[mi][ni][3] + ba1 + f1.y;
                *(unsigned*)(rt + row * M4_LDB + col)       = pk2h(r00, r01);
                *(unsigned*)(rt + (row + 8) * M4_LDB + col) = pk2h(r10, r11);
            }
        }
    }
    __syncthreads();

    {
        unsigned wa = smem_u32(wA);
        for (int i = tid; i < 128 * 16; i += 512) {
            int r = i >> 4, c = i & 15;
            cpasync16(wa + r * 272 + c * 16, g_o2h + r * 128 + c * 8);
        }
        CP_COMMIT();
    }

    // ---- phase 2: h1 = gelu(o1 * rt + b1) ----
    ZACC();
    gemm_t<8, M4_LDB>(wB, rt, acc, rbase, cbase, l);
    {
        float b10 = bias[128 + rbase + lr],      b11 = bias[128 + rbase + lr + 8];
        float b12 = bias[128 + rbase + 16 + lr], b13 = bias[128 + rbase + 16 + lr + 8];
#pragma unroll
        for (int mi = 0; mi < 2; mi++) {
            float ba0 = mi ? b12 : b10, ba1 = mi ? b13 : b11;
#pragma unroll
            for (int ni = 0; ni < 8; ni++) {
                acc[mi][ni][0] += ba0;
                acc[mi][ni][1] += ba0;
                acc[mi][ni][2] += ba1;
                acc[mi][ni][3] += ba1;
                gelu2(acc[mi][ni][0], acc[mi][ni][1]);
                gelu2(acc[mi][ni][2], acc[mi][ni][3]);
            }
        }
    }
    __syncthreads();
#pragma unroll
    for (int mi = 0; mi < 2; mi++) {
        int row = rbase + mi * 16 + lr;
#pragma unroll
        for (int ni = 0; ni < 8; ni++) {
            int col = cbase + ni * 8 + lc * 2;
            *(unsigned*)(rt + row * M4_LDB + col)       = pk2h(acc[mi][ni][0], acc[mi][ni][1]);
            *(unsigned*)(rt + (row + 8) * M4_LDB + col) = pk2h(acc[mi][ni][2], acc[mi][ni][3]);
        }
    }
    CP_WAIT(0);
    __syncthreads();

    // ---- phase 3: out = o2 * h1 + b2 + x ----
    ZACC();
    gemm_t<8, M4_LDB>(wA, rt, acc, rbase, cbase, l);
    {
        float b20 = bias[256 + rbase + lr],      b21 = bias[256 + rbase + lr + 8];
        float b22 = bias[256 + rbase + 16 + lr], b23 = bias[256 + rbase + 16 + lr + 8];
        float* ob = out + (size_t)b * CCH * NTOK + n0;
#pragma unroll
        for (int mi = 0; mi < 2; mi++) {
            int row = rbase + mi * 16 + lr;
            float ba0 = mi ? b22 : b20, ba1 = mi ? b23 : b21;
#pragma unroll
            for (int ni = 0; ni < 8; ni++) {
                int col = cbase + ni * 8 + lc * 2;
                __half2 xv0 = *(const __half2*)(xt + row * M4_LDB + col);
                __half2 xv1 = *(const __half2*)(xt + (row + 8) * M4_LDB + col);
                float2 f0 = __half22float2(xv0), f1 = __half22float2(xv1);
                float2 o0, o1v;
                o0.x = acc[mi][ni][0] + ba0 + f0.x;
                o0.y = acc[mi][ni][1] + ba0 + f0.y;
                o1v.x = acc[mi][ni][2] + ba1 + f1.x;
                o1v.y = acc[mi][ni][3] + ba1 + f1.y;
                *(float2*)(ob + (size_t)row * NTOK + col) = o0;
                *(float2*)(ob + (size_t)(row + 8) * NTOK + col) = o1v;
            }
        }
    }
}

// ---------------- launch ----------------
extern "C" void kernel_launch(void* const* d_in, const int* in_sizes, int n_in,
                              void* d_out, int out_size) {
    const float* x     = (const float*)d_in[0];
    const float* qkv_w = (const float*)d_in[1];
    const float* qkv_b = (const float*)d_in[2];
    const float* o1_w  = (const float*)d_in[3];
    const float* o1_b  = (const float*)d_in[4];
    const float* o2_w  = (const float*)d_in[5];
    const float* o2_b  = (const float*)d_in[6];
    const float* kln_w = (const float*)d_in[7];
    const float* kln_b = (const float*)d_in[8];
    const float* vln_w = (const float*)d_in[9];
    const float* vln_b = (const float*)d_in[10];
    float* out = (float*)d_out;

    cudaFuncSetAttribute(kv_kernel, cudaFuncAttributeMaxDynamicSharedMemorySize, KVS_SMEM);
    cudaFuncSetAttribute(main_kernel, cudaFuncAttributeMaxDynamicSharedMemorySize, M4_SMEM);

    prep_kernel<<<128, 256>>>(qkv_w, o1_w, o2_w);

    dim3 g2(NTOK / (128 * KV_TILES), BATCH);
    kv_kernel<<<g2, 512, KVS_SMEM>>>(x, qkv_b, kln_w, kln_b, vln_w, vln_b);

    dim3 gc(HEADS, BATCH);
    compose_kernel<<<gc, 128>>>(qkv_w, qkv_b);

    dim3 g4(NTOK / 256, BATCH);
    main_kernel<<<g4, 512, M4_SMEM>>>(o1_b, o2_b, out);
}

// round 11
// speedup vs baseline: 1.0467x; 1.0467x over previous
#include <cuda_runtime.h>
#include <cuda_fp16.h>

#define BATCH 8
#define CCH   128
#define NTOK  16384
#define HEADS 8
#define LN_EPS 1e-5f

// ---------------- device scratch ----------------
__device__ float  g_kv[BATCH * HEADS * 16 * 16];
__device__ __half g_wkv[256 * 128];
__device__ __half g_o1h[128 * 128];
__device__ __half g_o2h[128 * 128];
__device__ __half g_meff[BATCH * 128 * 128];
__device__ float  g_meffb[BATCH * 128];
__device__ __half g_x16[(size_t)BATCH * CCH * NTOK];

// ---------------- helpers ----------------
__device__ __forceinline__ unsigned pk2h(float a, float b) {
    __half2 h = __floats2half2_rn(a, b);
    return *reinterpret_cast<unsigned*>(&h);
}

__device__ __forceinline__ void mma16816h(float* c, const unsigned* a, const unsigned* b) {
    asm volatile(
        "mma.sync.aligned.m16n8k16.row.col.f32.f16.f16.f32 "
        "{%0,%1,%2,%3}, {%4,%5,%6,%7}, {%8,%9}, {%0,%1,%2,%3};\n"
        : "+f"(c[0]), "+f"(c[1]), "+f"(c[2]), "+f"(c[3])
        : "r"(a[0]), "r"(a[1]), "r"(a[2]), "r"(a[3]), "r"(b[0]), "r"(b[1]));
}

__device__ __forceinline__ unsigned smem_u32(const void* p) {
    return (unsigned)__cvta_generic_to_shared(p);
}

__device__ __forceinline__ void ldsm4(unsigned& r0, unsigned& r1, unsigned& r2, unsigned& r3,
                                      unsigned addr) {
    asm volatile("ldmatrix.sync.aligned.m8n8.x4.shared.b16 {%0,%1,%2,%3}, [%4];\n"
                 : "=r"(r0), "=r"(r1), "=r"(r2), "=r"(r3) : "r"(addr));
}

__device__ __forceinline__ void ldsm4t(unsigned& r0, unsigned& r1, unsigned& r2, unsigned& r3,
                                       unsigned addr) {
    asm volatile("ldmatrix.sync.aligned.m8n8.x4.trans.shared.b16 {%0,%1,%2,%3}, [%4];\n"
                 : "=r"(r0), "=r"(r1), "=r"(r2), "=r"(r3) : "r"(addr));
}

__device__ __forceinline__ void cpasync16(unsigned s, const void* g) {
    asm volatile("cp.async.cg.shared.global [%0], [%1], 16;\n" :: "r"(s), "l"(g));
}
#define CP_COMMIT() asm volatile("cp.async.commit_group;\n")
#define CP_WAIT(n)  asm volatile("cp.async.wait_group %0;\n" :: "n"(n))

__device__ __forceinline__ float rsqrt_fast(float x) {
    float r;
    asm("rsqrt.approx.f32 %0, %1;\n" : "=f"(r) : "f"(x));
    return r;
}

// fast erf: Abramowitz-Stegun 7.1.26 (R9-proven scalar form)
__device__ __forceinline__ float fast_erf(float x) {
    float ax = fabsf(x);
    float t = __fdividef(1.f, fmaf(0.3275911f, ax, 1.f));
    float p = fmaf(1.061405429f, t, -1.453152027f);
    p = fmaf(p, t, 1.421413741f);
    p = fmaf(p, t, -0.284496736f);
    p = fmaf(p, t, 0.254829592f);
    p *= t;
    float r = 1.f - p * __expf(-ax * ax);
    return copysignf(r, x);
}

// Output-layout GEMM: C[c_out rows][token cols] = A[c_out][k=128] * B[k=128][t].
template <int NI8, int LDB>
__device__ __forceinline__ void gemm_t(const __half* __restrict__ A,
                                       const __half* __restrict__ B,
                                       float (&acc)[2][NI8][4], int rbase, int cbase, int lane) {
    unsigned a_addr = smem_u32(A + (rbase + (lane & 15)) * 136 + ((lane >> 4) << 3));
    unsigned b_addr = smem_u32(B + (lane & 15) * LDB + cbase + ((lane >> 4) << 3));
#pragma unroll
    for (int kc = 0; kc < 128; kc += 16) {
        unsigned a[2][4];
        ldsm4(a[0][0], a[0][1], a[0][2], a[0][3], a_addr);
        ldsm4(a[1][0], a[1][1], a[1][2], a[1][3], a_addr + 16 * 136 * 2);
#pragma unroll
        for (int g = 0; g < NI8 / 2; g++) {
            unsigned b0, b1, b2, b3;
            ldsm4t(b0, b1, b2, b3, b_addr + g * 32);
            unsigned bl[2] = {b0, b1}, bh[2] = {b2, b3};
            mma16816h(acc[0][2 * g],     a[0], bl);
            mma16816h(acc[1][2 * g],     a[1], bl);
            mma16816h(acc[0][2 * g + 1], a[0], bh);
            mma16816h(acc[1][2 * g + 1], a[1], bh);
        }
        a_addr += 32;
        b_addr += 16 * LDB * 2;
    }
}

// ---------------- kernel 0: weight prep ----------------
__global__ void prep_kernel(const float* __restrict__ qkv_w,
                            const float* __restrict__ o1_w,
                            const float* __restrict__ o2_w) {
    int idx = blockIdx.x * blockDim.x + threadIdx.x;
    int nthr = gridDim.x * blockDim.x;
    for (int i = idx; i < BATCH * HEADS * 16 * 16; i += nthr) g_kv[i] = 0.f;
    for (int i = idx; i < 256 * 128; i += nthr) {
        int r = i >> 7, c = i & 127;
        int h = r >> 5, j = r & 31;
        int src = (j < 16) ? (48 * h + 16 + j) : (48 * h + 32 + (j - 16));
        g_wkv[i] = __float2half_rn(qkv_w[src * 128 + c]);
    }
    for (int i = idx; i < 128 * 128; i += nthr) {
        g_o1h[i] = __float2half_rn(o1_w[i]);
        g_o2h[i] = __float2half_rn(o2_w[i]);
    }
}

// ---------------- kernel 1: x->fp16 + k,v projection + register-LN + register-kv MMA ----------------
// 512 threads, 2 tiles of 128 tokens, x staged through smem via cp.async (LDG overlapped).
#define KVS_WT    0
#define KVS_XT0   (256 * 136 * 2)
#define KVS_XT1   (KVS_XT0 + 128 * 136 * 2)
#define KVS_STAGE (KVS_XT1 + 128 * 136 * 2)          // fp32 stage: 128 x 128 floats
#define KVS_QB    (KVS_STAGE + 128 * 128 * 4)
#define KVS_SMEM  (KVS_QB + 256 * 4)

__global__ void __launch_bounds__(512, 1) kv_kernel(const float* __restrict__ x,
                                                    const float* __restrict__ qkv_b,
                                                    const float* __restrict__ kln_w,
                                                    const float* __restrict__ kln_b,
                                                    const float* __restrict__ vln_w,
                                                    const float* __restrict__ vln_b) {
    extern __shared__ char smem[];
    __half* Wt = (__half*)(smem + KVS_WT);
    __half* xt0 = (__half*)(smem + KVS_XT0);
    __half* xt1 = (__half*)(smem + KVS_XT1);
    float* stg = (float*)(smem + KVS_STAGE);
    float* qb = (float*)(smem + KVS_QB);

    int tid = threadIdx.x;
    int b = blockIdx.y;
    const float* xb = x + (size_t)b * CCH * NTOK;
    __half* x16b = g_x16 + (size_t)b * CCH * NTOK;
    int n0base = blockIdx.x * 256;

    // one group: weights + stage(tile 0)
    {
        unsigned wt = smem_u32(Wt);
        for (int i = tid; i < 256 * 16; i += 512) {
            int r = i >> 4, c = i & 15;
            cpasync16(wt + r * 272 + c * 16, g_wkv + r * 128 + c * 8);
        }
        unsigned sa = smem_u32(stg);
        for (int i = tid; i < 128 * 32; i += 512) {
            int r = i >> 5, c = i & 31;
            cpasync16(sa + r * 512 + c * 16, xb + (size_t)r * NTOK + n0base + c * 4);
        }
        CP_COMMIT();
    }
    if (tid < 256) {
        int h = tid >> 5, j = tid & 31;
        int src_r = (j < 16) ? (48 * h + 16 + j) : (48 * h + 32 + (j - 16));
        qb[tid] = qkv_b[src_r];
    }

    int w = tid >> 5, l = tid & 31;
    int lr = l >> 2, lc = l & 3;
    int mw = w >> 1;      // head
    int nw = w & 1;       // token half
    int rbase = mw * 32, cbase = nw * 64;

    float lw[2][2], lb[2][2];
    lw[0][0] = kln_w[mw * 16 + lr];     lw[0][1] = kln_w[mw * 16 + lr + 8];
    lb[0][0] = kln_b[mw * 16 + lr];     lb[0][1] = kln_b[mw * 16 + lr + 8];
    lw[1][0] = vln_w[mw * 16 + lr];     lw[1][1] = vln_w[mw * 16 + lr + 8];
    lb[1][0] = vln_b[mw * 16 + lr];     lb[1][1] = vln_b[mw * 16 + lr + 8];

    float acc2[2][4];
#pragma unroll
    for (int e = 0; e < 2; e++)
#pragma unroll
        for (int q = 0; q < 4; q++) acc2[e][q] = 0.f;

#pragma unroll
    for (int tile = 0; tile < 2; tile++) {
        int n0 = n0base + tile * 128;
        __half* xt = tile ? xt1 : xt0;

        CP_WAIT(0);
        __syncthreads();   // stage (and, tile 0, weights) ready

        // convert stage -> xt (fp16) + g_x16
#pragma unroll
        for (int k = 0; k < 8; k++) {
            int i = tid + k * 512;
            int r = i >> 5, c4 = i & 31;
            float4 v = *(const float4*)(stg + r * 128 + c4 * 4);
            __half2 h0 = __floats2half2_rn(v.x, v.y);
            __half2 h1 = __floats2half2_rn(v.z, v.w);
            uint2 u;
            u.x = *reinterpret_cast<unsigned*>(&h0);
            u.y = *reinterpret_cast<unsigned*>(&h1);
            *(uint2*)(xt + r * 136 + c4 * 4) = u;
            *(uint2*)(x16b + (size_t)r * NTOK + n0 + c4 * 4) = u;
        }
        __syncthreads();   // xt complete; stage fully consumed

        if (tile == 0) {
            // prefetch tile 1 stage; overlaps the whole tile-0 GEMM
            unsigned sa = smem_u32(stg);
            for (int i = tid; i < 128 * 32; i += 512) {
                int r = i >> 5, c = i & 31;
                cpasync16(sa + r * 512 + c * 16, xb + (size_t)r * NTOK + n0base + 128 + c * 4);
            }
            CP_COMMIT();
        }

        float acc[2][8][4];
#pragma unroll
        for (int a_ = 0; a_ < 2; a_++)
#pragma unroll
            for (int b_ = 0; b_ < 8; b_++)
#pragma unroll
                for (int c_ = 0; c_ < 4; c_++) acc[a_][b_][c_] = 0.f;

        gemm_t<8, 136>(Wt, xt, acc, rbase, cbase, l);

        float q0 = qb[rbase + lr],      q1 = qb[rbase + lr + 8];
        float q2 = qb[rbase + 16 + lr], q3 = qb[rbase + 16 + lr + 8];
#pragma unroll
        for (int ni = 0; ni < 8; ni++) {
            acc[0][ni][0] += q0; acc[0][ni][1] += q0;
            acc[0][ni][2] += q1; acc[0][ni][3] += q1;
            acc[1][ni][0] += q2; acc[1][ni][1] += q2;
            acc[1][ni][2] += q3; acc[1][ni][3] += q3;
        }

        // register LayerNorm over d=16 (ddof=1, eps on std), half2-packed butterflies
        unsigned kf[8][2], vf[8][2];
#pragma unroll
        for (int mi = 0; mi < 2; mi++) {
#pragma unroll
            for (int ni = 0; ni < 8; ni++) {
                float* c = acc[mi][ni];
                __half2 s2 = __floats2half2_rn(c[0] + c[2], c[1] + c[3]);
                __half2 q2h = __floats2half2_rn(fmaf(c[0], c[0], c[2] * c[2]),
                                                fmaf(c[1], c[1], c[3] * c[3]));
                unsigned su = *reinterpret_cast<unsigned*>(&s2);
                unsigned qu = *reinterpret_cast<unsigned*>(&q2h);
#pragma unroll
                for (int m = 4; m <= 16; m <<= 1) {
                    unsigned so = __shfl_xor_sync(0xffffffffu, su, m);
                    unsigned qo = __shfl_xor_sync(0xffffffffu, qu, m);
                    __half2 rs2 = __hadd2(*reinterpret_cast<__half2*>(&su),
                                          *reinterpret_cast<__half2*>(&so));
                    __half2 rq2 = __hadd2(*reinterpret_cast<__half2*>(&qu),
                                          *reinterpret_cast<__half2*>(&qo));
                    su = *reinterpret_cast<unsigned*>(&rs2);
                    qu = *reinterpret_cast<unsigned*>(&rq2);
                }
                float2 s = __half22float2(*reinterpret_cast<__half2*>(&su));
                float2 q = __half22float2(*reinterpret_cast<__half2*>(&qu));
                float ma = s.x * (1.f / 16.f);
                float va = fmaxf((q.x - 16.f * ma * ma) * (1.f / 15.f), 1e-12f);
                float rsa = rsqrt_fast(va);
                float ia = fmaf(-LN_EPS * rsa, rsa, rsa);
                float mb = s.y * (1.f / 16.f);
                float vb = fmaxf((q.y - 16.f * mb * mb) * (1.f / 15.f), 1e-12f);
                float rsb = rsqrt_fast(vb);
                float ib = fmaf(-LN_EPS * rsb, rsb, rsb);
                float n0v = lw[mi][0] * ((c[0] - ma) * ia) + lb[mi][0];
                float n1v = lw[mi][0] * ((c[1] - mb) * ib) + lb[mi][0];
                float n2v = lw[mi][1] * ((c[2] - ma) * ia) + lb[mi][1];
                float n3v = lw[mi][1] * ((c[3] - mb) * ib) + lb[mi][1];
                unsigned lo = pk2h(n0v, n1v);
                unsigned hi = pk2h(n2v, n3v);
                if (mi == 0) { kf[ni][0] = lo; kf[ni][1] = hi; }
                else         { vf[ni][0] = lo; vf[ni][1] = hi; }
            }
        }

        // kv outer product entirely in registers
#pragma unroll
        for (int tc = 0; tc < 4; tc++) {
            unsigned a[4] = {kf[2 * tc][0], kf[2 * tc][1], kf[2 * tc + 1][0], kf[2 * tc + 1][1]};
            unsigned b0[2] = {vf[2 * tc][0], vf[2 * tc + 1][0]};
            unsigned b1[2] = {vf[2 * tc][1], vf[2 * tc + 1][1]};
            mma16816h(acc2[0], a, b0);
            mma16816h(acc2[1], a, b1);
        }
    }

    float* base = g_kv + (size_t)(b * HEADS + mw) * 256;
#pragma unroll
    for (int eh = 0; eh < 2; eh++) {
        int e0 = eh * 8 + lc * 2;
        atomicAdd(base + lr * 16 + e0,           acc2[eh][0]);
        atomicAdd(base + lr * 16 + e0 + 1,       acc2[eh][1]);
        atomicAdd(base + (lr + 8) * 16 + e0,     acc2[eh][2]);
        atomicAdd(base + (lr + 8) * 16 + e0 + 1, acc2[eh][3]);
    }
}

// ---------------- kernel 2: compose Meff_b = Wq o kv / N (512 threads) ----------------
__global__ void compose_kernel(const float* __restrict__ qkv_w, const float* __restrict__ qkv_b) {
    __shared__ float kvs[256];
    int g = blockIdx.x, b = blockIdx.y;
    int tid = threadIdx.x;
    int ci = tid & 127;
    int eg = tid >> 7;          // 0..3, each handles 4 e values

    if (tid < 256)
        kvs[tid] = g_kv[(b * HEADS + g) * 256 + tid] * (1.f / (float)NTOK);
    __syncthreads();

    if (tid < 16) {
        float s = 0.f;
#pragma unroll
        for (int d = 0; d < 16; d++) s += qkv_b[48 * g + d] * kvs[d * 16 + tid];
        g_meffb[b * 128 + g * 16 + tid] = s;
    }

    float wq[16];
#pragma unroll
    for (int d = 0; d < 16; d++) wq[d] = qkv_w[(48 * g + d) * 128 + ci];

    __half* mdst = g_meff + ((size_t)b * 128 + g * 16) * 128 + ci;
#pragma unroll
    for (int ee = 0; ee < 4; ee++) {
        int e = eg * 4 + ee;
        float s = 0.f;
#pragma unroll
        for (int d = 0; d < 16; d++) s += wq[d] * kvs[d * 16 + e];
        mdst[e * 128] = __float2half_rn(s);
    }
}

// ---------------- kernel 3: fused av + residual + o1 + gelu + o2 + residual ----------------
#define M4_LDB  264
#define M4_XT   0
#define M4_RT   (128 * M4_LDB * 2)
#define M4_WA   (2 * 128 * M4_LDB * 2)
#define M4_WB   (M4_WA + 128 * 136 * 2)
#define M4_BIAS (M4_WB + 128 * 136 * 2)
#define M4_SMEM (M4_BIAS + 3 * 128 * 4)

__global__ void __launch_bounds__(512, 1) main_kernel(const float* __restrict__ o1_b,
                                                      const float* __restrict__ o2_b,
                                                      float* __restrict__ out) {
    extern __shared__ char smem[];
    __half* xt = (__half*)(smem + M4_XT);
    __half* rt = (__half*)(smem + M4_RT);
    __half* wA = (__half*)(smem + M4_WA);
    __half* wB = (__half*)(smem + M4_WB);
    float* bias = (float*)(smem + M4_BIAS);

    int tid = threadIdx.x;
    int b = blockIdx.y;
    int n0 = blockIdx.x * 256;

    {
        unsigned wa = smem_u32(wA), xa = smem_u32(xt);
        const __half* msrc = g_meff + (size_t)b * 128 * 128;
        const __half* xsrc = g_x16 + (size_t)b * CCH * NTOK + n0;
        for (int i = tid; i < 128 * 16; i += 512) {
            int r = i >> 4, c = i & 15;
            cpasync16(wa + r * 272 + c * 16, msrc + r * 128 + c * 8);
        }
        for (int i = tid; i < 128 * 32; i += 512) {
            int r = i >> 5, c = i & 31;
            cpasync16(xa + r * (M4_LDB * 2) + c * 16, xsrc + (size_t)r * NTOK + c * 8);
        }
        CP_COMMIT();
        unsigned wb = smem_u32(wB);
        for (int i = tid; i < 128 * 16; i += 512) {
            int r = i >> 4, c = i & 15;
            cpasync16(wb + r * 272 + c * 16, g_o1h + r * 128 + c * 8);
        }
        CP_COMMIT();
    }
    if (tid < 128) {
        bias[tid] = g_meffb[b * 128 + tid];
        bias[128 + tid] = o1_b[tid];
        bias[256 + tid] = o2_b[tid];
    }
    CP_WAIT(1);
    __syncthreads();

    int w = tid >> 5, l = tid & 31;
    int lr = l >> 2, lc = l & 3;
    int mw = w >> 2, nw = w & 3;
    int rbase = mw * 32, cbase = nw * 64;

    float acc[2][8][4];
#define ZACC() { _Pragma("unroll") for (int a_=0;a_<2;a_++) _Pragma("unroll") for (int b_=0;b_<8;b_++) _Pragma("unroll") for (int c_=0;c_<4;c_++) acc[a_][b_][c_]=0.f; }

    // ---- phase 1: rt = Meff*x + meffb + x ----
    ZACC();
    gemm_t<8, M4_LDB>(wA, xt, acc, rbase, cbase, l);
    {
        float bm0 = bias[rbase + lr],      bm1 = bias[rbase + lr + 8];
        float bm2 = bias[rbase + 16 + lr], bm3 = bias[rbase + 16 + lr + 8];
#pragma unroll
        for (int mi = 0; mi < 2; mi++) {
            int row = rbase + mi * 16 + lr;
            float ba0 = mi ? bm2 : bm0, ba1 = mi ? bm3 : bm1;
#pragma unroll
            for (int ni = 0; ni < 8; ni++) {
                int col = cbase + ni * 8 + lc * 2;
                __half2 xv0 = *(const __half2*)(xt + row * M4_LDB + col);
                __half2 xv1 = *(const __half2*)(xt + (row + 8) * M4_LDB + col);
                float2 f0 = __half22float2(xv0), f1 = __half22float2(xv1);
                float r00 = acc[mi][ni][0] + ba0 + f0.x;
                float r01 = acc[mi][ni][1] + ba0 + f0.y;
                float r10 = acc[mi][ni][2] + ba1 + f1.x;
                float r11 = acc[mi][ni][3] + ba1 + f1.y;
                *(unsigned*)(rt + row * M4_LDB + col)       = pk2h(r00, r01);
                *(unsigned*)(rt + (row + 8) * M4_LDB + col) = pk2h(r10, r11);
            }
        }
    }
    __syncthreads();

    {
        unsigned wa = smem_u32(wA);
        for (int i = tid; i < 128 * 16; i += 512) {
            int r = i >> 4, c = i & 15;
            cpasync16(wa + r * 272 + c * 16, g_o2h + r * 128 + c * 8);
        }
        CP_COMMIT();
    }

    // ---- phase 2: h1 = gelu(o1 * rt + b1) ----
    ZACC();
    gemm_t<8, M4_LDB>(wB, rt, acc, rbase, cbase, l);
    {
        float b10 = bias[128 + rbase + lr],      b11 = bias[128 + rbase + lr + 8];
        float b12 = bias[128 + rbase + 16 + lr], b13 = bias[128 + rbase + 16 + lr + 8];
#pragma unroll
        for (int mi = 0; mi < 2; mi++) {
            float ba0 = mi ? b12 : b10, ba1 = mi ? b13 : b11;
#pragma unroll
            for (int ni = 0; ni < 8; ni++) {
#pragma unroll
                for (int q = 0; q < 4; q++) {
                    float h = acc[mi][ni][q] + ((q < 2) ? ba0 : ba1);
                    acc[mi][ni][q] = 0.5f * h * (1.f + fast_erf(h * 0.70710678118654752f));
                }
            }
        }
    }
    __syncthreads();
#pragma unroll
    for (int mi = 0; mi < 2; mi++) {
        int row = rbase + mi * 16 + lr;
#pragma unroll
        for (int ni = 0; ni < 8; ni++) {
            int col = cbase + ni * 8 + lc * 2;
            *(unsigned*)(rt + row * M4_LDB + col)       = pk2h(acc[mi][ni][0], acc[mi][ni][1]);
            *(unsigned*)(rt + (row + 8) * M4_LDB + col) = pk2h(acc[mi][ni][2], acc[mi][ni][3]);
        }
    }
    CP_WAIT(0);
    __syncthreads();

    // ---- phase 3: out = o2 * h1 + b2 + x (streaming stores) ----
    ZACC();
    gemm_t<8, M4_LDB>(wA, rt, acc, rbase, cbase, l);
    {
        float b20 = bias[256 + rbase + lr],      b21 = bias[256 + rbase + lr + 8];
        float b22 = bias[256 + rbase + 16 + lr], b23 = bias[256 + rbase + 16 + lr + 8];
        float* ob = out + (size_t)b * CCH * NTOK + n0;
#pragma unroll
        for (int mi = 0; mi < 2; mi++) {
            int row = rbase + mi * 16 + lr;
            float ba0 = mi ? b22 : b20, ba1 = mi ? b23 : b21;
#pragma unroll
            for (int ni = 0; ni < 8; ni++) {
                int col = cbase + ni * 8 + lc * 2;
                __half2 xv0 = *(const __half2*)(xt + row * M4_LDB + col);
                __half2 xv1 = *(const __half2*)(xt + (row + 8) * M4_LDB + col);
                float2 f0 = __half22float2(xv0), f1 = __half22float2(xv1);
                float2 o0, o1v;
                o0.x = acc[mi][ni][0] + ba0 + f0.x;
                o0.y = acc[mi][ni][1] + ba0 + f0.y;
                o1v.x = acc[mi][ni][2] + ba1 + f1.x;
                o1v.y = acc[mi][ni][3] + ba1 + f1.y;
                __stcs((float2*)(ob + (size_t)row * NTOK + col), o0);
                __stcs((float2*)(ob + (size_t)(row + 8) * NTOK + col), o1v);
            }
        }
    }
}

// ---------------- launch ----------------
extern "C" void kernel_launch(void* const* d_in, const int* in_sizes, int n_in,
                              void* d_out, int out_size) {
    const float* x     = (const float*)d_in[0];
    const float* qkv_w = (const float*)d_in[1];
    const float* qkv_b = (const float*)d_in[2];
    const float* o1_w  = (const float*)d_in[3];
    const float* o1_b  = (const float*)d_in[4];
    const float* o2_w  = (const float*)d_in[5];
    const float* o2_b  = (const float*)d_in[6];
    const float* kln_w = (const float*)d_in[7];
    const float* kln_b = (const float*)d_in[8];
    const float* vln_w = (const float*)d_in[9];
    const float* vln_b = (const float*)d_in[10];
    float* out = (float*)d_out;

    cudaFuncSetAttribute(kv_kernel, cudaFuncAttributeMaxDynamicSharedMemorySize, KVS_SMEM);
    cudaFuncSetAttribute(main_kernel, cudaFuncAttributeMaxDynamicSharedMemorySize, M4_SMEM);

    prep_kernel<<<128, 256>>>(qkv_w, o1_w, o2_w);

    dim3 g2(NTOK / 256, BATCH);
    kv_kernel<<<g2, 512, KVS_SMEM>>>(x, qkv_b, kln_w, kln_b, vln_w, vln_b);

    dim3 gc(HEADS, BATCH);
    compose_kernel<<<gc, 512>>>(qkv_w, qkv_b);

    dim3 g4(NTOK / 256, BATCH);
    main_kernel<<<g4, 512, M4_SMEM>>>(o1_b, o2_b, out);
}